// round 16
// baseline (speedup 1.0000x reference)
#include <cuda_runtime.h>
#include <math.h>

#define D        64
#define MQ       32
#define TK       64
#define TOPK     32
#define NTMAX    64
#define NROWMAX  4096
#define NEG_INF  (-3.402823466e38f)

typedef unsigned long long u64;

// global scratch (static; no allocation)
__device__ u64   g_bits[NROWMAX * NTMAX];     // mask bitmask per (row, tile)
__device__ float g_tsc [NROWMAX * TOPK];
__device__ int   g_tix [NROWMAX * TOPK];      // GLOBAL v-row index (b*L + l)
__device__ float g_cnt [NROWMAX];
__device__ float g_vsum[NROWMAX * D];

__device__ __forceinline__ void fma2(u64& d, u64 a, u64 b) {
    asm("fma.rn.f32x2 %0, %1, %2, %0;" : "+l"(d) : "l"(a), "l"(b));
}
__device__ __forceinline__ float2 up2(u64 a) {
    float2 r;
    asm("mov.b64 {%0,%1}, %2;" : "=f"(r.x), "=f"(r.y) : "l"(a));
    return r;
}
__device__ __forceinline__ void madd2(u64& a0, u64& a1, unsigned t, u64 vx, u64 vy) {
    asm volatile("{\n\t.reg .pred p;\n\tsetp.ne.u32 p, %2, 0;\n\t"
                 "@p add.rn.f32x2 %0, %0, %3;\n\t"
                 "@p add.rn.f32x2 %1, %1, %4;\n\t}"
                 : "+l"(a0), "+l"(a1) : "r"(t), "l"(vx), "l"(vy));
}
__device__ __forceinline__ void cp16(void* s, const void* g) {
    unsigned sa = (unsigned)__cvta_generic_to_shared(s);
    asm volatile("cp.async.cg.shared.global [%0], [%1], 16;" :: "r"(sa), "l"(g));
}

// ================= kernel 1: scores + exact top-32 =================
struct __align__(16) Smem1 {
    float Qs[MQ][D + 4];
    float Ks[2][TK][D + 4];
    float Ss[2][MQ][D + 4];
    float tsc[MQ][TOPK + 1];
    int   tix[MQ][TOPK + 1];
    u64   Mbits[2][MQ];
    u64   cand[2][MQ];
    float thr[MQ];
};

__global__ __launch_bounds__(256)
void ga_score(const float* __restrict__ q, const float* __restrict__ k,
              const int* __restrict__ mask, int B, int Lq, int L)
{
    extern __shared__ unsigned char smem_raw[];
    Smem1* S = reinterpret_cast<Smem1*>(smem_raw);

    const int tid  = threadIdx.x;
    const int b    = blockIdx.y;
    const int q0g  = blockIdx.x * MQ;
    const int row0 = b * Lq + q0g;
    const int NT   = L / TK;
    const int t15  = tid & 15;
    const int qa   = 4 * (tid >> 4);            // score warps 0-3 (tid<128): 4q x 4k

    for (int j = tid; j < MQ * D; j += 256) {
        int qi = j >> 6, d = j & 63;
        S->Qs[qi][d] = q[((size_t)row0 + qi) * D + d] * 0.125f;
    }
    for (int j = tid; j < MQ * TOPK; j += 256) {
        S->tsc[j >> 5][j & 31] = NEG_INF;
        S->tix[j >> 5][j & 31] = -1;
    }
    if (tid < MQ) {
        S->thr[tid]     = NEG_INF;
        S->cand[0][tid] = 0ull;
        S->cand[1][tid] = 0ull;
    }

    const size_t kb = (size_t)b * L * D;

    // prologue: K tile 0 + Mbits[0] (+ export)
    for (int j = tid; j < 1024; j += 256) {
        int i = j >> 4, c4 = (j & 15) << 2;
        *(float4*)&S->Ks[0][i][c4] = *(const float4*)(k + kb + (size_t)i * D + c4);
    }
    {
        int qi = tid >> 3, c8 = (tid & 7) << 3;
        const int4* mp = (const int4*)(mask + (size_t)(row0 + qi) * L + c8);
        int4 m0 = mp[0], m1 = mp[1];
        u64 bits = ((u64)(m0.x != 0) << c8)       | ((u64)(m0.y != 0) << (c8 + 1))
                 | ((u64)(m0.z != 0) << (c8 + 2)) | ((u64)(m0.w != 0) << (c8 + 3))
                 | ((u64)(m1.x != 0) << (c8 + 4)) | ((u64)(m1.y != 0) << (c8 + 5))
                 | ((u64)(m1.z != 0) << (c8 + 6)) | ((u64)(m1.w != 0) << (c8 + 7));
        #pragma unroll
        for (int off = 1; off < 8; off <<= 1)
            bits |= __shfl_xor_sync(0xFFFFFFFFu, bits, off);
        if ((tid & 7) == 0) {
            S->Mbits[0][qi] = bits;
            g_bits[(size_t)(row0 + qi) * NTMAX] = bits;
        }
    }
    __syncthreads();

    float thrL = NEG_INF;
    int   minpos = 0;
    float cntL = 0.0f;

    for (int t = 0; t < NT; t++) {
        const int p  = t & 1;
        const int pn = p ^ 1;
        const int l0 = t * TK;

        if (tid < 128) {
            // ---- score warps: 4q x 4k, strided k rows ----
            float thr4[4];
            u64   Mb4[4];
            #pragma unroll
            for (int qi = 0; qi < 4; qi++) {
                thr4[qi] = S->thr[qa + qi];
                Mb4[qi]  = S->Mbits[p][qa + qi];
            }
            u64 sp[4][4];
            #pragma unroll
            for (int qi = 0; qi < 4; qi++)
                #pragma unroll
                for (int j = 0; j < 4; j++) sp[qi][j] = 0ull;

            #pragma unroll 2
            for (int d = 0; d < D; d += 4) {
                ulonglong2 Qr[4];
                #pragma unroll
                for (int qi = 0; qi < 4; qi++)
                    Qr[qi] = *(const ulonglong2*)&S->Qs[qa + qi][d];
                #pragma unroll
                for (int j = 0; j < 4; j++) {
                    ulonglong2 Kj = *(const ulonglong2*)&S->Ks[p][t15 + 16 * j][d];
                    #pragma unroll
                    for (int qi = 0; qi < 4; qi++) {
                        fma2(sp[qi][j], Qr[qi].x, Kj.x);
                        fma2(sp[qi][j], Qr[qi].y, Kj.y);
                    }
                }
            }
            u64 w4[4] = {0ull, 0ull, 0ull, 0ull};
            #pragma unroll
            for (int j = 0; j < 4; j++) {
                int kp = t15 + 16 * j;
                #pragma unroll
                for (int qi = 0; qi < 4; qi++) {
                    float2 pv = up2(sp[qi][j]);
                    float  s  = pv.x + pv.y;
                    S->Ss[p][qa + qi][kp] = s;
                    if (s > thr4[qi] && ((Mb4[qi] >> kp) & 1ull)) w4[qi] |= 1ull << kp;
                }
            }
            #pragma unroll
            for (int qi = 0; qi < 4; qi++)
                if (w4[qi]) atomicOr(&S->cand[p][qa + qi], w4[qi]);
        } else if (tid < 160) {
            // ---- merge warp: consume tile t-1, prefetch+export Mbits t+1 ----
            const int qq = tid - 128;
            if (t > 0) {
                u64 w = S->cand[pn][qq];
                S->cand[pn][qq] = 0ull;
                cntL += (float)__popcll(S->Mbits[pn][qq]);
                const int l0p = l0 - TK;
                while (w) {
                    int kk = __ffsll((long long)w) - 1;
                    w &= w - 1ull;
                    float s = S->Ss[pn][qq][kk];
                    if (s > thrL) {
                        S->tsc[qq][minpos] = s;
                        S->tix[qq][minpos] = b * L + l0p + kk;   // global v row
                        float nm = S->tsc[qq][0]; int np = 0;
                        #pragma unroll
                        for (int i = 1; i < TOPK; i++) {
                            float ti = S->tsc[qq][i];
                            if (ti < nm) { nm = ti; np = i; }
                        }
                        thrL = nm; minpos = np;
                    }
                }
                S->thr[qq] = thrL;
            }
            if (t < NT - 1) {
                const int4* mp = (const int4*)(mask + (size_t)(row0 + qq) * L + l0 + TK);
                u64 bits = 0ull;
                #pragma unroll
                for (int c4 = 0; c4 < 16; c4++) {
                    int4 mm = mp[c4];
                    bits |= ((u64)(mm.x != 0) << (4 * c4))
                          | ((u64)(mm.y != 0) << (4 * c4 + 1))
                          | ((u64)(mm.z != 0) << (4 * c4 + 2))
                          | ((u64)(mm.w != 0) << (4 * c4 + 3));
                }
                S->Mbits[pn][qq] = bits;
                g_bits[(size_t)(row0 + qq) * NTMAX + t + 1] = bits;
            }
        } else {
            // ---- loader warps (3): cp.async next K tile ----
            if (t < NT - 1) {
                const int lt = tid - 160;                 // 0..95
                const size_t base = kb + (size_t)(l0 + TK) * D;
                for (int j = lt; j < 1024; j += 96) {
                    int i = j >> 4, c4 = (j & 15) << 2;
                    cp16(&S->Ks[pn][i][c4], k + base + (size_t)i * D + c4);
                }
                asm volatile("cp.async.commit_group;");
                asm volatile("cp.async.wait_group 0;");
            }
        }
        __syncthreads();
    }

    // final merge (last tile)
    if (tid >= 128 && tid < 160) {
        const int qq = tid - 128;
        const int pl = (NT - 1) & 1;
        u64 w = S->cand[pl][qq];
        cntL += (float)__popcll(S->Mbits[pl][qq]);
        const int l0p = L - TK;
        while (w) {
            int kk = __ffsll((long long)w) - 1;
            w &= w - 1ull;
            float s = S->Ss[pl][qq][kk];
            if (s > thrL) {
                S->tsc[qq][minpos] = s;
                S->tix[qq][minpos] = b * L + l0p + kk;
                float nm = S->tsc[qq][0]; int np = 0;
                #pragma unroll
                for (int i = 1; i < TOPK; i++) {
                    float ti = S->tsc[qq][i];
                    if (ti < nm) { nm = ti; np = i; }
                }
                thrL = nm; minpos = np;
            }
        }
        g_cnt[row0 + qq] = cntL;
    }
    __syncthreads();

    // export heap
    for (int j = tid; j < MQ * TOPK; j += 256) {
        int qq = j >> 5, i = j & 31;
        g_tsc[(size_t)(row0 + qq) * TOPK + i] = S->tsc[qq][i];
        g_tix[(size_t)(row0 + qq) * TOPK + i] = S->tix[qq][i];
    }
}

// ================= kernel 2: masked V mean-pool sums =================
struct __align__(16) Smem2 {
    float Vs[2][TK][D];
    float Sv[MQ][D + 4];
};

__global__ __launch_bounds__(256)
void ga_vsum(const float* __restrict__ v, int B, int Lq, int L)
{
    __shared__ Smem2 S;
    const int tid  = threadIdx.x;
    const int b    = blockIdx.y;
    const int row0 = b * Lq + blockIdx.x * MQ;
    const int NT   = L / TK;

    const int vhalf = tid >> 7;                 // 0: keys 0-31, 1: keys 32-63
    const int w128  = tid & 127;
    const int qb    = 4 * (w128 >> 4);
    const int dc    = 4 * (w128 & 15);

    const size_t kb = (size_t)b * L * D;

    // prologue: V tile 0 + Mbits(t=0)
    for (int j = tid; j < 1024; j += 256) {
        int i = j >> 4, c4 = (j & 15) << 2;
        *(float4*)&S.Vs[0][i][c4] = *(const float4*)(v + kb + (size_t)i * D + c4);
    }
    u64 Mb[4];
    #pragma unroll
    for (int qi = 0; qi < 4; qi++)
        Mb[qi] = g_bits[(size_t)(row0 + qb + qi) * NTMAX];
    __syncthreads();

    u64 mv[8];
    #pragma unroll
    for (int i = 0; i < 8; i++) mv[i] = 0ull;

    for (int t = 0; t < NT; t++) {
        const int p  = t & 1;
        const int pn = p ^ 1;

        if (t < NT - 1) {
            const size_t base = kb + (size_t)(t + 1) * TK * D;
            #pragma unroll
            for (int r = 0; r < 4; r++) {
                int j = tid + 256 * r;
                int i = j >> 4, c4 = (j & 15) << 2;
                cp16(&S.Vs[pn][i][c4], v + base + (size_t)i * D + c4);
            }
            asm volatile("cp.async.commit_group;");
        }

        // accumulate over this tile's 32-key half (r10-proven loop)
        unsigned mw[4];
        #pragma unroll
        for (int qi = 0; qi < 4; qi++)
            mw[qi] = vhalf ? (unsigned)(Mb[qi] >> 32) : (unsigned)Mb[qi];
        const float* vrow = &S.Vs[p][vhalf << 5][dc];
        #pragma unroll
        for (int l = 0; l < 32; l++) {
            ulonglong2 v2 = *(const ulonglong2*)(vrow + l * D);
            #pragma unroll
            for (int qi = 0; qi < 4; qi++) {
                unsigned tb = mw[qi] & (1u << l);
                madd2(mv[2 * qi], mv[2 * qi + 1], tb, v2.x, v2.y);
            }
        }

        if (t < NT - 1) {
            #pragma unroll
            for (int qi = 0; qi < 4; qi++)
                Mb[qi] = g_bits[(size_t)(row0 + qb + qi) * NTMAX + t + 1];
            asm volatile("cp.async.wait_group 0;");
        }
        __syncthreads();
    }

    // combine halves + export
    if (vhalf == 0) {
        #pragma unroll
        for (int qi = 0; qi < 4; qi++) {
            float2 a = up2(mv[2 * qi]);
            float2 c = up2(mv[2 * qi + 1]);
            *(float4*)&S.Sv[qb + qi][dc] = make_float4(a.x, a.y, c.x, c.y);
        }
    }
    __syncthreads();
    if (vhalf == 1) {
        #pragma unroll
        for (int qi = 0; qi < 4; qi++) {
            float4 cur = *(float4*)&S.Sv[qb + qi][dc];
            float2 a = up2(mv[2 * qi]);
            float2 c = up2(mv[2 * qi + 1]);
            cur.x += a.x; cur.y += a.y; cur.z += c.x; cur.w += c.y;
            *(float4*)&S.Sv[qb + qi][dc] = cur;
        }
    }
    __syncthreads();
    for (int j = tid; j < MQ * D; j += 256) {
        int qi = j >> 6, d = j & 63;
        g_vsum[(size_t)(row0 + qi) * D + d] = S.Sv[qi][d];
    }
}

// ================= kernel 3: softmax + gather + combine =================
__global__ __launch_bounds__(256)
void ga_epi(const float* __restrict__ v, float* __restrict__ out, int N)
{
    const int wid  = threadIdx.x >> 5;
    const int lane = threadIdx.x & 31;
    const int n    = blockIdx.x * 8 + wid;
    if (n >= N) return;

    float s  = g_tsc[(size_t)n * TOPK + lane];
    int   ix = g_tix[(size_t)n * TOPK + lane];
    bool valid = (ix >= 0);
    float sv = valid ? s : NEG_INF;
    float m = sv;
    #pragma unroll
    for (int off = 16; off > 0; off >>= 1)
        m = fmaxf(m, __shfl_xor_sync(0xFFFFFFFFu, m, off));
    float e = valid ? expf(s - m) : 0.0f;
    float den = e;
    #pragma unroll
    for (int off = 16; off > 0; off >>= 1)
        den += __shfl_xor_sync(0xFFFFFFFFu, den, off);
    float w = (den > 0.0f) ? (e / den) : 0.0f;

    float a0 = 0.0f, a1 = 0.0f;
    #pragma unroll 1
    for (int i = 0; i < TOPK; i++) {
        float wi = __shfl_sync(0xFFFFFFFFu, w, i);
        int   ii = __shfl_sync(0xFFFFFFFFu, ix, i);
        if (ii >= 0) {
            const float* vr = v + (size_t)ii * D;
            a0 = fmaf(wi, vr[lane],      a0);
            a1 = fmaf(wi, vr[lane + 32], a1);
        }
    }
    float c = fmaxf(g_cnt[n], 1.0f);
    out[(size_t)n * D + lane]      = g_vsum[(size_t)n * D + lane]      / c + a0;
    out[(size_t)n * D + lane + 32] = g_vsum[(size_t)n * D + lane + 32] / c + a1;
}

extern "C" void kernel_launch(void* const* d_in, const int* in_sizes, int n_in,
                              void* d_out, int out_size)
{
    const float* q = (const float*)d_in[0];
    const float* k = (const float*)d_in[1];
    const float* v = (const float*)d_in[2];
    const int*   mask = (const int*)d_in[3];
    float* out = (float*)d_out;

    int N    = in_sizes[0] / D;    // B * Lq
    int Ktot = in_sizes[1] / D;    // B * L
    int L    = in_sizes[3] / N;
    int B    = Ktot / L;
    int Lq   = N / B;

    int smem1 = (int)sizeof(Smem1);
    cudaFuncSetAttribute(ga_score, cudaFuncAttributeMaxDynamicSharedMemorySize, smem1);

    dim3 grid(Lq / MQ, B);
    ga_score<<<grid, 256, smem1>>>(q, k, mask, B, Lq, L);
    ga_vsum<<<grid, 256>>>(v, B, Lq, L);
    ga_epi<<<(N + 7) / 8, 256>>>(v, out, N);
}

// round 17
// speedup vs baseline: 1.1574x; 1.1574x over previous
#include <cuda_runtime.h>
#include <math.h>

#define D        64
#define MQ       16            // queries per block (both roles)
#define TK       64
#define TOPK     32
#define NROWMAX  4096
#define NEG_INF  (-3.402823466e38f)

typedef unsigned long long u64;

// global scratch (static; no allocation)
__device__ float g_tsc [NROWMAX * TOPK];
__device__ int   g_tix [NROWMAX * TOPK];      // GLOBAL v-row index (b*L + l)
__device__ float g_cnt [NROWMAX];
__device__ float g_vsum[NROWMAX * D];

__device__ __forceinline__ void fma2(u64& d, u64 a, u64 b) {
    asm("fma.rn.f32x2 %0, %1, %2, %0;" : "+l"(d) : "l"(a), "l"(b));
}
__device__ __forceinline__ float2 up2(u64 a) {
    float2 r;
    asm("mov.b64 {%0,%1}, %2;" : "=f"(r.x), "=f"(r.y) : "l"(a));
    return r;
}
__device__ __forceinline__ void madd2(u64& a0, u64& a1, unsigned t, u64 vx, u64 vy) {
    asm volatile("{\n\t.reg .pred p;\n\tsetp.ne.u32 p, %2, 0;\n\t"
                 "@p add.rn.f32x2 %0, %0, %3;\n\t"
                 "@p add.rn.f32x2 %1, %1, %4;\n\t}"
                 : "+l"(a0), "+l"(a1) : "r"(t), "l"(vx), "l"(vy));
}
__device__ __forceinline__ void cp16(void* s, const void* g) {
    unsigned sa = (unsigned)__cvta_generic_to_shared(s);
    asm volatile("cp.async.cg.shared.global [%0], [%1], 16;" :: "r"(sa), "l"(g));
}

// ---- shared-memory layouts (two roles share one dynamic allocation) ----
struct __align__(16) ScoreSm {
    float Qs[MQ][D + 4];
    float Ks[2][TK][D + 4];
    float Ss[2][MQ][D + 4];
    float tsc[MQ][TOPK + 1];
    int   tix[MQ][TOPK + 1];
    u64   Mbits[2][MQ];
    u64   cand[2][MQ];
    float thr[MQ];
};
struct __align__(16) VsumSm {
    float Vs[2][TK][D];
    float Sv[MQ][D + 4];
    u64   Mbits[2][MQ];
};

__global__ __launch_bounds__(256)
void ga_main(const float* __restrict__ q, const float* __restrict__ k,
             const float* __restrict__ v, const int* __restrict__ mask,
             int B, int Lq, int L)
{
    extern __shared__ unsigned char smem_raw[];

    const int tid  = threadIdx.x;
    const int b    = blockIdx.y;
    const int row0 = b * Lq + blockIdx.x * MQ;
    const int NT   = L / TK;
    const size_t kb = (size_t)b * L * D;

    if (blockIdx.z == 0) {
        // ======================= SCORE + TOP-K block =======================
        ScoreSm* S = reinterpret_cast<ScoreSm*>(smem_raw);
        const int t15 = tid & 15;
        const int qa  = 2 * ((tid & 127) >> 4);        // warps 0-3: 2q x 4k

        for (int j = tid; j < MQ * D; j += 256) {
            int qi = j >> 6, d = j & 63;
            S->Qs[qi][d] = q[((size_t)row0 + qi) * D + d] * 0.125f;
        }
        for (int j = tid; j < MQ * TOPK; j += 256) {
            S->tsc[j >> 5][j & 31] = NEG_INF;
            S->tix[j >> 5][j & 31] = -1;
        }
        if (tid < MQ) {
            S->thr[tid]     = NEG_INF;
            S->cand[0][tid] = 0ull;
            S->cand[1][tid] = 0ull;
        }
        // prologue: K tile 0 + Mbits[0]
        for (int j = tid; j < 1024; j += 256) {
            int i = j >> 4, c4 = (j & 15) << 2;
            *(float4*)&S->Ks[0][i][c4] = *(const float4*)(k + kb + (size_t)i * D + c4);
        }
        {
            int qi = tid >> 4, c4 = (tid & 15) << 2;
            int4 mm = *(const int4*)(mask + (size_t)(row0 + qi) * L + c4);
            u64 bits = ((u64)(mm.x != 0) << c4)       | ((u64)(mm.y != 0) << (c4 + 1))
                     | ((u64)(mm.z != 0) << (c4 + 2)) | ((u64)(mm.w != 0) << (c4 + 3));
            #pragma unroll
            for (int off = 1; off < 16; off <<= 1)
                bits |= __shfl_xor_sync(0xFFFFFFFFu, bits, off);
            if ((tid & 15) == 0) S->Mbits[0][qi] = bits;
        }
        __syncthreads();

        float thrL = NEG_INF;
        int   minpos = 0;
        float cntL = 0.0f;

        for (int t = 0; t < NT; t++) {
            const int p  = t & 1;
            const int pn = p ^ 1;
            const int l0 = t * TK;

            if (tid < 128) {
                const float thr0 = S->thr[qa];
                const float thr1 = S->thr[qa + 1];
                const u64   Mb0  = S->Mbits[p][qa];
                const u64   Mb1  = S->Mbits[p][qa + 1];
                u64 sp0[4], sp1[4];
                #pragma unroll
                for (int j = 0; j < 4; j++) { sp0[j] = 0ull; sp1[j] = 0ull; }
                #pragma unroll 4
                for (int d = 0; d < D; d += 4) {
                    ulonglong2 Q0 = *(const ulonglong2*)&S->Qs[qa][d];
                    ulonglong2 Q1 = *(const ulonglong2*)&S->Qs[qa + 1][d];
                    #pragma unroll
                    for (int j = 0; j < 4; j++) {
                        ulonglong2 Kj = *(const ulonglong2*)&S->Ks[p][t15 + 16 * j][d];
                        fma2(sp0[j], Q0.x, Kj.x);
                        fma2(sp0[j], Q0.y, Kj.y);
                        fma2(sp1[j], Q1.x, Kj.x);
                        fma2(sp1[j], Q1.y, Kj.y);
                    }
                }
                u64 w0 = 0ull, w1 = 0ull;
                #pragma unroll
                for (int j = 0; j < 4; j++) {
                    int kp = t15 + 16 * j;
                    float2 p0 = up2(sp0[j]);
                    float  s0 = p0.x + p0.y;
                    S->Ss[p][qa][kp] = s0;
                    if (s0 > thr0 && ((Mb0 >> kp) & 1ull)) w0 |= 1ull << kp;
                    float2 p1 = up2(sp1[j]);
                    float  s1 = p1.x + p1.y;
                    S->Ss[p][qa + 1][kp] = s1;
                    if (s1 > thr1 && ((Mb1 >> kp) & 1ull)) w1 |= 1ull << kp;
                }
                if (w0) atomicOr(&S->cand[p][qa],     w0);
                if (w1) atomicOr(&S->cand[p][qa + 1], w1);
            } else if (tid < 160) {
                const int qq = tid - 128;
                if (qq < MQ) {
                    if (t > 0) {
                        u64 w = S->cand[pn][qq];
                        S->cand[pn][qq] = 0ull;
                        cntL += (float)__popcll(S->Mbits[pn][qq]);
                        const int l0p = l0 - TK;
                        while (w) {
                            int kk = __ffsll((long long)w) - 1;
                            w &= w - 1ull;
                            float s = S->Ss[pn][qq][kk];
                            if (s > thrL) {
                                S->tsc[qq][minpos] = s;
                                S->tix[qq][minpos] = b * L + l0p + kk;
                                float nm = S->tsc[qq][0]; int np = 0;
                                #pragma unroll
                                for (int i = 1; i < TOPK; i++) {
                                    float ti = S->tsc[qq][i];
                                    if (ti < nm) { nm = ti; np = i; }
                                }
                                thrL = nm; minpos = np;
                            }
                        }
                        S->thr[qq] = thrL;
                    }
                    if (t < NT - 1) {
                        const int4* mp = (const int4*)(mask + (size_t)(row0 + qq) * L + l0 + TK);
                        u64 bits = 0ull;
                        #pragma unroll
                        for (int c4 = 0; c4 < 16; c4++) {
                            int4 mm = mp[c4];
                            bits |= ((u64)(mm.x != 0) << (4 * c4))
                                  | ((u64)(mm.y != 0) << (4 * c4 + 1))
                                  | ((u64)(mm.z != 0) << (4 * c4 + 2))
                                  | ((u64)(mm.w != 0) << (4 * c4 + 3));
                        }
                        S->Mbits[pn][qq] = bits;
                    }
                }
            } else {
                if (t < NT - 1) {
                    const int lt = tid - 160;                 // 0..95
                    const size_t base = kb + (size_t)(l0 + TK) * D;
                    for (int j = lt; j < 1024; j += 96) {
                        int i = j >> 4, c4 = (j & 15) << 2;
                        cp16(&S->Ks[pn][i][c4], k + base + (size_t)i * D + c4);
                    }
                    asm volatile("cp.async.commit_group;");
                    asm volatile("cp.async.wait_group 0;");
                }
            }
            __syncthreads();
        }

        // final merge (last tile)
        if (tid >= 128 && tid < 128 + MQ) {
            const int qq = tid - 128;
            const int pl = (NT - 1) & 1;
            u64 w = S->cand[pl][qq];
            cntL += (float)__popcll(S->Mbits[pl][qq]);
            const int l0p = L - TK;
            while (w) {
                int kk = __ffsll((long long)w) - 1;
                w &= w - 1ull;
                float s = S->Ss[pl][qq][kk];
                if (s > thrL) {
                    S->tsc[qq][minpos] = s;
                    S->tix[qq][minpos] = b * L + l0p + kk;
                    float nm = S->tsc[qq][0]; int np = 0;
                    #pragma unroll
                    for (int i = 1; i < TOPK; i++) {
                        float ti = S->tsc[qq][i];
                        if (ti < nm) { nm = ti; np = i; }
                    }
                    thrL = nm; minpos = np;
                }
            }
            g_cnt[row0 + qq] = cntL;
        }
        __syncthreads();

        for (int j = tid; j < MQ * TOPK; j += 256) {
            int qq = j >> 5, i = j & 31;
            g_tsc[(size_t)(row0 + qq) * TOPK + i] = S->tsc[qq][i];
            g_tix[(size_t)(row0 + qq) * TOPK + i] = S->tix[qq][i];
        }
    } else {
        // ======================= MASKED V-SUM block =======================
        VsumSm* S = reinterpret_cast<VsumSm*>(smem_raw);
        const int vhalf = tid >> 7;                 // 0: keys 0-31, 1: keys 32-63
        const int w128  = tid & 127;
        const int qb    = 2 * (w128 >> 4);          // 0..14 (2q tile)
        const int dc    = 4 * (w128 & 15);

        // prologue: V tile 0 + Mbits[0]
        for (int j = tid; j < 1024; j += 256) {
            int i = j >> 4, c4 = (j & 15) << 2;
            *(float4*)&S->Vs[0][i][c4] = *(const float4*)(v + kb + (size_t)i * D + c4);
        }
        {
            int qi = tid >> 4, c4 = (tid & 15) << 2;
            int4 mm = *(const int4*)(mask + (size_t)(row0 + qi) * L + c4);
            u64 bits = ((u64)(mm.x != 0) << c4)       | ((u64)(mm.y != 0) << (c4 + 1))
                     | ((u64)(mm.z != 0) << (c4 + 2)) | ((u64)(mm.w != 0) << (c4 + 3));
            #pragma unroll
            for (int off = 1; off < 16; off <<= 1)
                bits |= __shfl_xor_sync(0xFFFFFFFFu, bits, off);
            if ((tid & 15) == 0) S->Mbits[0][qi] = bits;
        }
        __syncthreads();

        u64 mv[4];                                  // 2q x 4d accumulators
        #pragma unroll
        for (int i = 0; i < 4; i++) mv[i] = 0ull;

        for (int t = 0; t < NT; t++) {
            const int p  = t & 1;
            const int pn = p ^ 1;

            if (t < NT - 1) {
                const size_t base = kb + (size_t)(t + 1) * TK * D;
                #pragma unroll
                for (int r = 0; r < 4; r++) {
                    int j = tid + 256 * r;
                    int i = j >> 4, c4 = (j & 15) << 2;
                    cp16(&S->Vs[pn][i][c4], v + base + (size_t)i * D + c4);
                }
                asm volatile("cp.async.commit_group;");
            }

            // accumulate tile t (registers mw read before building next bits)
            unsigned mw0, mw1;
            {
                u64 M0 = S->Mbits[p][qb];
                u64 M1 = S->Mbits[p][qb + 1];
                mw0 = vhalf ? (unsigned)(M0 >> 32) : (unsigned)M0;
                mw1 = vhalf ? (unsigned)(M1 >> 32) : (unsigned)M1;
            }
            const float* vrow = &S->Vs[p][vhalf << 5][dc];
            #pragma unroll
            for (int l = 0; l < 32; l++) {
                ulonglong2 v2 = *(const ulonglong2*)(vrow + l * D);
                unsigned tb0 = mw0 & (1u << l);
                unsigned tb1 = mw1 & (1u << l);
                madd2(mv[0], mv[1], tb0, v2.x, v2.y);
                madd2(mv[2], mv[3], tb1, v2.x, v2.y);
            }

            // build Mbits for t+1 (writes pn buffer; p still valid for others)
            if (t < NT - 1) {
                int qi = tid >> 4, c4 = (tid & 15) << 2;
                int4 mm = *(const int4*)(mask + (size_t)(row0 + qi) * L + (t + 1) * TK + c4);
                u64 bits = ((u64)(mm.x != 0) << c4)       | ((u64)(mm.y != 0) << (c4 + 1))
                         | ((u64)(mm.z != 0) << (c4 + 2)) | ((u64)(mm.w != 0) << (c4 + 3));
                #pragma unroll
                for (int off = 1; off < 16; off <<= 1)
                    bits |= __shfl_xor_sync(0xFFFFFFFFu, bits, off);
                if ((tid & 15) == 0) S->Mbits[pn][qi] = bits;
                asm volatile("cp.async.wait_group 0;");
            }
            __syncthreads();
        }

        // combine halves + export
        if (vhalf == 0) {
            float2 a = up2(mv[0]), c = up2(mv[1]);
            *(float4*)&S->Sv[qb][dc] = make_float4(a.x, a.y, c.x, c.y);
            float2 e = up2(mv[2]), f = up2(mv[3]);
            *(float4*)&S->Sv[qb + 1][dc] = make_float4(e.x, e.y, f.x, f.y);
        }
        __syncthreads();
        if (vhalf == 1) {
            float4 cur = *(float4*)&S->Sv[qb][dc];
            float2 a = up2(mv[0]), c = up2(mv[1]);
            cur.x += a.x; cur.y += a.y; cur.z += c.x; cur.w += c.y;
            *(float4*)&S->Sv[qb][dc] = cur;
            float4 cur2 = *(float4*)&S->Sv[qb + 1][dc];
            float2 e = up2(mv[2]), f = up2(mv[3]);
            cur2.x += e.x; cur2.y += e.y; cur2.z += f.x; cur2.w += f.y;
            *(float4*)&S->Sv[qb + 1][dc] = cur2;
        }
        __syncthreads();
        for (int j = tid; j < MQ * D; j += 256) {
            int qi = j >> 6, d = j & 63;
            g_vsum[(size_t)(row0 + qi) * D + d] = S->Sv[qi][d];
        }
    }
}

// ================= epilogue: softmax + gather + combine =================
__global__ __launch_bounds__(256)
void ga_epi(const float* __restrict__ v, float* __restrict__ out, int N)
{
    const int wid  = threadIdx.x >> 5;
    const int lane = threadIdx.x & 31;
    const int n    = blockIdx.x * 8 + wid;
    if (n >= N) return;

    float s  = g_tsc[(size_t)n * TOPK + lane];
    int   ix = g_tix[(size_t)n * TOPK + lane];
    bool valid = (ix >= 0);
    float sv = valid ? s : NEG_INF;
    float m = sv;
    #pragma unroll
    for (int off = 16; off > 0; off >>= 1)
        m = fmaxf(m, __shfl_xor_sync(0xFFFFFFFFu, m, off));
    float e = valid ? expf(s - m) : 0.0f;
    float den = e;
    #pragma unroll
    for (int off = 16; off > 0; off >>= 1)
        den += __shfl_xor_sync(0xFFFFFFFFu, den, off);
    float w = (den > 0.0f) ? (e / den) : 0.0f;

    float a0 = 0.0f, a1 = 0.0f;
    #pragma unroll 1
    for (int i = 0; i < TOPK; i++) {
        float wi = __shfl_sync(0xFFFFFFFFu, w, i);
        int   ii = __shfl_sync(0xFFFFFFFFu, ix, i);
        if (ii >= 0) {
            const float* vr = v + (size_t)ii * D;
            a0 = fmaf(wi, vr[lane],      a0);
            a1 = fmaf(wi, vr[lane + 32], a1);
        }
    }
    float c = fmaxf(g_cnt[n], 1.0f);
    out[(size_t)n * D + lane]      = g_vsum[(size_t)n * D + lane]      / c + a0;
    out[(size_t)n * D + lane + 32] = g_vsum[(size_t)n * D + lane + 32] / c + a1;
}

extern "C" void kernel_launch(void* const* d_in, const int* in_sizes, int n_in,
                              void* d_out, int out_size)
{
    const float* q = (const float*)d_in[0];
    const float* k = (const float*)d_in[1];
    const float* v = (const float*)d_in[2];
    const int*   mask = (const int*)d_in[3];
    float* out = (float*)d_out;

    int N    = in_sizes[0] / D;    // B * Lq
    int Ktot = in_sizes[1] / D;    // B * L
    int L    = in_sizes[3] / N;
    int B    = Ktot / L;
    int Lq   = N / B;

    int smem = (int)(sizeof(ScoreSm) > sizeof(VsumSm) ? sizeof(ScoreSm) : sizeof(VsumSm));
    cudaFuncSetAttribute(ga_main, cudaFuncAttributeMaxDynamicSharedMemorySize, smem);

    dim3 grid(Lq / MQ, B, 2);
    ga_main<<<grid, 256, smem>>>(q, k, v, mask, B, Lq, L);
    ga_epi<<<(N + 7) / 8, 256>>>(v, out, N);
}